// round 12
// baseline (speedup 1.0000x reference)
#include <cuda_runtime.h>

#define Nn 8
#define Cc 64
#define Hh 256
#define Ww 256
#define Pp 16          // cluster: 8 col-groups x 2 ch-groups
#define NT 256         // 8 warps: conv warp = 4 out-ch x 32 cols
#define HW (Hh*Ww)

// float-index smem offsets
#define WS_F 0                          // weights 6144 (own 32 out-ch)
#define FBA_F(p) (6144 + (p)*2176)      // fn windows [64ch][34], parity, batch A
#define FBB_F(p) (10496 + (p)*2176)
#define YA_F(p)  (14848 + (p)*2176)     // y windows, parity
#define YB_F(p)  (19200 + (p)*2176)
#define MLA_F(p) (23552 + (p)*1024)     // mail [16 rank][64], parity
#define MLB_F(p) (25600 + (p)*1024)
#define MRA_F 27648                     // mean[64] | rstd[64]
#define MRB_F 27776
#define XWA_F(p) (27904 + (p)*2176)     // residual windows, parity
#define XWB_F(p) (32256 + (p)*2176)
#define SM_TOT 36608
#define SMEM_BYTES (SM_TOT*4)           // 146 KB

__device__ float g_stack[(size_t)Nn * Cc * Hh * Ww];

extern __shared__ float sm[];

__device__ __forceinline__ void carr() {
    asm volatile("barrier.cluster.arrive.aligned;" ::: "memory");
}
__device__ __forceinline__ void cwait() {
    asm volatile("barrier.cluster.wait.aligned;" ::: "memory");
}
__device__ __forceinline__ unsigned mapa_rank(unsigned laddr, unsigned rank) {
    unsigned ra;
    asm("mapa.shared::cluster.u32 %0, %1, %2;" : "=r"(ra) : "r"(laddr), "r"(rank));
    return ra;
}
__device__ __forceinline__ void st_cl_f32(unsigned a, float v) {
    asm volatile("st.shared::cluster.f32 [%0], %1;" :: "r"(a), "f"(v) : "memory");
}
__device__ __forceinline__ void st_cl_b64(unsigned a, unsigned long long v) {
    asm volatile("st.shared::cluster.b64 [%0], %1;" :: "r"(a), "l"(v) : "memory");
}

// ---- packed f32x2 helpers ----
__device__ __forceinline__ unsigned long long splat2(float a) {
    unsigned long long r; unsigned u = __float_as_uint(a);
    asm("mov.b64 %0, {%1, %1};" : "=l"(r) : "r"(u));
    return r;
}
__device__ __forceinline__ void fma2(unsigned long long& d, unsigned long long a, unsigned long long b) {
    asm("fma.rn.f32x2 %0, %1, %2, %0;" : "+l"(d) : "l"(a), "l"(b));
}
__device__ __forceinline__ unsigned long long add2(unsigned long long a, unsigned long long b) {
    unsigned long long d;
    asm("add.rn.f32x2 %0, %1, %2;" : "=l"(d) : "l"(a), "l"(b));
    return d;
}
__device__ __forceinline__ unsigned long long mul2(unsigned long long a, unsigned long long b) {
    unsigned long long d;
    asm("mul.rn.f32x2 %0, %1, %2;" : "=l"(d) : "l"(a), "l"(b));
    return d;
}
__device__ __forceinline__ void unpack2(unsigned long long v, float& lo, float& hi) {
    unsigned ul, uh;
    asm("mov.b64 {%0, %1}, %2;" : "=r"(ul), "=r"(uh) : "l"(v));
    lo = __uint_as_float(ul); hi = __uint_as_float(uh);
}

struct Peers {
    unsigned pbP, pbL0, pbL1, pbR0, pbR1;
    unsigned pbAll[16];
    unsigned rank;
    int hasL, hasR;
};

// stage one row's full 64ch x 34col window (edge-masked) into smem
__device__ __forceinline__ void load_window(const float* __restrict__ src,
    int row, int w0, int tid, float* __restrict__ dsm)
{
#pragma unroll
    for (int it = 0; it < 9; it++) {
        int idx = tid + it * NT;
        if (idx < 2176) {
            int ch = idx / 34;
            int c  = idx - ch * 34;
            int gcol = w0 - 1 + c;
            dsm[idx] = (gcol >= 0 && gcol < Ww)
                     ? src[(size_t)ch * HW + (size_t)row * Ww + gcol] : 0.f;
        }
    }
}

// conv (own 32 out-ch x 32 cols) + publish y (local/partner/halos) + mail push
__device__ __forceinline__ void conv_push(
    const float* __restrict__ fbR, const float* __restrict__ Ws,
    float* __restrict__ yL, unsigned yBB, unsigned mlB,
    int lane, int ob, int cbase, const Peers& P)
{
    unsigned long long acc0 = 0ull, acc1 = 0ull;
#pragma unroll 8
    for (int i = 0; i < Cc; i++) {
        float a0 = fbR[i * 34 + lane];
        float a1 = fbR[i * 34 + lane + 1];
        float a2 = fbR[i * 34 + lane + 2];
        unsigned long long s0 = splat2(a0), s1 = splat2(a1), s2 = splat2(a2);
        const float* wp = Ws + i * 96 + ob;
        ulonglong2 t0 = *(const ulonglong2*)(wp);
        ulonglong2 t1 = *(const ulonglong2*)(wp + 32);
        ulonglong2 t2 = *(const ulonglong2*)(wp + 64);
        fma2(acc0, s0, t0.x); fma2(acc1, s0, t0.y);
        fma2(acc0, s1, t1.x); fma2(acc1, s1, t1.y);
        fma2(acc0, s2, t2.x); fma2(acc1, s2, t2.y);
    }
    float av[4];
    unpack2(acc0, av[0], av[1]);
    unpack2(acc1, av[2], av[3]);
#pragma unroll
    for (int k = 0; k < 4; k++) {
        int o = (cbase + ob + k) * 34 + 1 + lane;
        yL[o] = av[k];
        st_cl_f32(P.pbP + yBB + (unsigned)o * 4u, av[k]);
    }
    if (lane == 0 && P.hasL) {
#pragma unroll
        for (int k = 0; k < 4; k++) {
            unsigned o = yBB + (unsigned)((cbase + ob + k) * 34 + 33) * 4u;
            st_cl_f32(P.pbL0 + o, av[k]); st_cl_f32(P.pbL1 + o, av[k]);
        }
    }
    if (lane == 31 && P.hasR) {
#pragma unroll
        for (int k = 0; k < 4; k++) {
            unsigned o = yBB + (unsigned)((cbase + ob + k) * 34 + 0) * 4u;
            st_cl_f32(P.pbR0 + o, av[k]); st_cl_f32(P.pbR1 + o, av[k]);
        }
    }
    // butterfly reduce over 32 cols, then all-to-all mail (15 remote ranks)
    unsigned long long s0r = acc0, s1r = acc1;
    unsigned long long q0r = mul2(acc0, acc0), q1r = mul2(acc1, acc1);
#pragma unroll
    for (int off = 16; off >= 1; off >>= 1) {
        s0r = add2(s0r, __shfl_xor_sync(0xffffffffu, s0r, off));
        s1r = add2(s1r, __shfl_xor_sync(0xffffffffu, s1r, off));
        q0r = add2(q0r, __shfl_xor_sync(0xffffffffu, q0r, off));
        q1r = add2(q1r, __shfl_xor_sync(0xffffffffu, q1r, off));
    }
    if (lane < 4) {
        int j   = lane & 1;
        int isq = lane >> 1;
        unsigned long long val = isq ? (j ? q1r : q0r) : (j ? s1r : s0r);
        unsigned moff = mlB + (unsigned)((int)P.rank * 64 + isq * 32 + ob + 2 * j) * 4u;
        *(unsigned long long*)((char*)sm + moff) = val;   // local slot
#pragma unroll
        for (int p2 = 0; p2 < 16; p2++)
            if (p2 != (int)P.rank) st_cl_b64(P.pbAll[p2] + moff, val);
    }
}

// stats (all 64 ch from local mail) + replicated epilogue -> fbW (local only)
__device__ __forceinline__ void stats_epi(
    const float* __restrict__ ml, float* __restrict__ mr,
    const float* __restrict__ yb, const float* __restrict__ xw,
    float* __restrict__ fbW, int tid, int g, int ch_e, int cs, int clen)
{
    if (tid < 64) {
        int par = tid >> 5;
        float sv = 0.f, qv = 0.f;
#pragma unroll
        for (int gg = 0; gg < 8; gg++) {
            int r2 = 2 * gg + par;
            sv += ml[r2 * 64 + (tid & 31)];
            qv += ml[r2 * 64 + 32 + (tid & 31)];
        }
        float mean = sv * (1.f / 256.f);
        float var  = qv * (1.f / 256.f) - mean * mean;
        mr[tid]      = mean;
        mr[64 + tid] = rsqrtf(var + 1e-5f);
    }
    __syncthreads();
    float m  = mr[ch_e];
    float rs = mr[64 + ch_e];
#pragma unroll
    for (int j = 0; j < 9; j++) {
        if (j < clen) {
            int c = cs + j;
            float y = yb[ch_e * 34 + c];
            float v = (y - m) * rs;
            v = v > 0.f ? v : (__expf(v) - 1.f);
            int pad = (g == 0 && c == 0) || (g == 7 && c == 33);
            fbW[ch_e * 34 + c] = pad ? 0.f : (v + xw[ch_e * 34 + c]);
        }
    }
}

// deferred own-block writeback of one row from the fn window
__device__ __forceinline__ void wb_row(const float* __restrict__ fbS,
    float* __restrict__ dst, int row, int ch_w, int cw, int w0)
{
    const float* fr = fbS + ch_w * 34 + 1 + cw;
    float4 v = make_float4(fr[0], fr[1], fr[2], fr[3]);
    *(float4*)(dst + (size_t)ch_w * HW + (size_t)row * Ww + w0 + cw) = v;
}

__global__ void __launch_bounds__(NT, 1) __cluster_dims__(Pp, 1, 1)
dirconv_kernel(const float* __restrict__ x, const float* __restrict__ Wg,
               float* __restrict__ out)
{
    float* Ws = sm;
    const unsigned smu = (unsigned)__cvta_generic_to_shared(sm);

    const int tid  = threadIdx.x;
    const int lane = tid & 31;
    const int warp = tid >> 5;
    const int ob   = warp * 4;
    unsigned rank;
    asm("mov.u32 %0, %%cluster_ctarank;" : "=r"(rank));
    const int g     = (int)(rank >> 1);
    const int cg    = (int)(rank & 1u);
    const int cbase = cg * 32;
    const int w0    = g * 32;
    const int cid   = blockIdx.x / Pp;
    const int hasL  = (g > 0), hasR = (g < 7);

    const float* xbA = x + (size_t)(2 * cid) * Cc * HW;
    const float* xbB = x + (size_t)(2 * cid + 1) * Cc * HW;
    float* stkA = g_stack + (size_t)(2 * cid) * Cc * HW;
    float* stkB = g_stack + (size_t)(2 * cid + 1) * Cc * HW;
    float* outA = out + (size_t)(2 * cid) * Cc * HW;
    float* outB = out + (size_t)(2 * cid + 1) * Cc * HW;

    Peers P;
    P.rank = rank; P.hasL = hasL; P.hasR = hasR;
    P.pbP  = mapa_rank(smu, rank ^ 1u);
    unsigned basr = rank & ~1u;
    P.pbL0 = mapa_rank(smu, hasL ? basr - 2u : 0u);
    P.pbL1 = mapa_rank(smu, hasL ? basr - 1u : 0u);
    P.pbR0 = mapa_rank(smu, hasR ? basr + 2u : 0u);
    P.pbR1 = mapa_rank(smu, hasR ? basr + 3u : 0u);
#pragma unroll
    for (int p2 = 0; p2 < 16; p2++) P.pbAll[p2] = mapa_rank(smu, (unsigned)p2);

    // stage weights: Ws[i*96 + tap*32 + ol] = W[cbase+ol][i][1][tap] (bias cancels in IN)
    for (int idx = tid; idx < 6144; idx += NT) {
        int i   = idx / 96;
        int rem = idx - i * 96;
        int tap = rem >> 5;
        int ol  = rem & 31;
        Ws[idx] = Wg[(size_t)(cbase + ol) * 576 + i * 9 + 3 + tap];
    }

    // init: f(0)=x(0) windows, stack row 0 (own block), residual windows for t=1
    load_window(xbA, 0, w0, tid, sm + FBA_F(0));
    load_window(xbB, 0, w0, tid, sm + FBB_F(0));
    load_window(xbA, 1, w0, tid, sm + XWA_F(1));
    load_window(xbB, 1, w0, tid, sm + XWB_F(1));
    for (int idx = tid; idx < 1024; idx += NT) {
        int ch = cbase + (idx >> 5);
        int c  = idx & 31;
        stkA[(size_t)ch * HW + w0 + c] = xbA[(size_t)ch * HW + w0 + c];
        stkB[(size_t)ch * HW + w0 + c] = xbB[(size_t)ch * HW + w0 + c];
    }
    __syncthreads();
    carr();   // priming phase (B,0)

    // epilogue mapping: thread -> (channel, col segment {9,9,8,8})
    const int ch_e = tid >> 2;
    const int seg  = tid & 3;
    const int cs   = (seg < 2) ? seg * 9 : 18 + (seg - 2) * 8;
    const int clen = (seg < 2) ? 9 : 8;
    // writeback mapping: thread -> (own channel, 4 cols)
    const int ch_w = cbase + (tid >> 3);
    const int cw   = (tid & 7) * 4;

    for (int t = 1; t <= 510; ++t) {
        const int p = t & 1;

        // ======== A half: conv(t) + pushes; wb(t-1); prefetch(t+1)
        conv_push(sm + FBA_F(p ^ 1), Ws, sm + YA_F(p),
                  (unsigned)(YA_F(p) * 4), (unsigned)(MLA_F(p) * 4),
                  lane, ob, cbase, P);
        if (t >= 2) {
            int pf = (t - 1) <= 255;
            int pr = pf ? (t - 1) : (511 - t);
            wb_row(sm + FBA_F(p ^ 1), pf ? stkA : outA, pr, ch_w, cw, w0);
            if (t == 256) wb_row(sm + FBA_F(p ^ 1), outA, 255, ch_w, cw, w0);
        }
        if (t < 510 && t != 255) {
            int tn = t + 1, nf = tn <= 255;
            load_window(nf ? xbA : stkA, nf ? tn : 510 - tn, w0, tid, sm + XWA_F(p ^ 1));
        }
        cwait();   // completes phase (B,t-1): mailB/yB parity p^1 delivered
        if (t == 256) load_window(stkA, 254, w0, tid, sm + XWA_F(0));
        if (t == 257) load_window(stkB, 254, w0, tid, sm + XWB_F(0));
        if (t >= 2)
            stats_epi(sm + MLB_F(p ^ 1), sm + MRB_F, sm + YB_F(p ^ 1),
                      sm + XWB_F(p ^ 1), sm + FBB_F(p ^ 1), tid, g, ch_e, cs, clen);
        carr();          // opens phase (A,t): releases this iter's A pushes
        __syncthreads(); // fbB(t-1) complete CTA-wide

        // ======== B half: conv(t) + pushes; wb(t-1); prefetch(t+1)
        conv_push(sm + FBB_F(p ^ 1), Ws, sm + YB_F(p),
                  (unsigned)(YB_F(p) * 4), (unsigned)(MLB_F(p) * 4),
                  lane, ob, cbase, P);
        if (t >= 2) {
            int pf = (t - 1) <= 255;
            int pr = pf ? (t - 1) : (511 - t);
            wb_row(sm + FBB_F(p ^ 1), pf ? stkB : outB, pr, ch_w, cw, w0);
            if (t == 256) wb_row(sm + FBB_F(p ^ 1), outB, 255, ch_w, cw, w0);
        }
        if (t < 510 && t != 255 && t != 256) {
            int tn = t + 1, nf = tn <= 255;
            load_window(nf ? xbB : stkB, nf ? tn : 510 - tn, w0, tid, sm + XWB_F(p ^ 1));
        }
        if (t == 256) {   // for t+1=257: row 253 (safe: wb(253) at iter 254)
            load_window(stkB, 253, w0, tid, sm + XWB_F(0 ^ 1));
        }
        cwait();   // completes phase (A,t): mailA/yA parity p delivered
        stats_epi(sm + MLA_F(p), sm + MRA_F, sm + YA_F(p),
                  sm + XWA_F(p), sm + FBA_F(p), tid, g, ch_e, cs, clen);
        carr();          // opens phase (B,t)
        __syncthreads(); // fbA(t) complete for next iter's conv_A
    }

    // tail: finish batch B step 510, then final row-0 writebacks
    cwait();   // completes phase (B,510)
    stats_epi(sm + MLB_F(0), sm + MRB_F, sm + YB_F(0),
              sm + XWB_F(0), sm + FBB_F(0), tid, g, ch_e, cs, clen);
    __syncthreads();
    wb_row(sm + FBA_F(0), outA, 0, ch_w, cw, w0);
    wb_row(sm + FBB_F(0), outB, 0, ch_w, cw, w0);
}

extern "C" void kernel_launch(void* const* d_in, const int* in_sizes, int n_in,
                              void* d_out, int out_size)
{
    (void)in_sizes; (void)n_in; (void)out_size;
    const float* x  = (const float*)d_in[0];
    const float* Wg = (const float*)d_in[1];
    // d_in[2] (bias) cancels through InstanceNorm — skipped.
    float* out = (float*)d_out;

    cudaStreamCaptureStatus cs2 = cudaStreamCaptureStatusNone;
    cudaStreamIsCapturing(0, &cs2);
    if (cs2 == cudaStreamCaptureStatusNone) {
        cudaFuncSetAttribute(dirconv_kernel,
                             cudaFuncAttributeNonPortableClusterSizeAllowed, 1);
        cudaFuncSetAttribute(dirconv_kernel,
                             cudaFuncAttributeMaxDynamicSharedMemorySize, SMEM_BYTES);
    }

    dirconv_kernel<<<(Nn / 2) * Pp, NT, SMEM_BYTES>>>(x, Wg, out);
}

// round 13
// speedup vs baseline: 1.6414x; 1.6414x over previous
#include <cuda_runtime.h>

#define Nn 8
#define Cc 64
#define Hh 256
#define Ww 256
#define Pp 8           // cluster: 8 column groups; CTA = all 64 out-ch x 32 cols
#define NT 256         // 8 warps: warp = 8 out-ch x 32 cols
#define HW (Hh*Ww)
#define FSTR 34

// float-index smem offsets
#define WS_F 0                          // weights [64 i][3 tap][64 o] = 12288
#define FB_F(p) (12288 + (p)*2176)      // fn window [64 ch][34], parity (LOCAL only)
#define ML_F(p) (16640 + (p)*1024)      // mail [8 rank][sum64|sq64], parity
#define YH_F(p) (18688 + (p)*128)       // y halo [64 ch][left,right], parity
#define MR_F 18944                      // mean[64] | rstd[64]
#define SM_TOT 19072
#define SMEM_BYTES (SM_TOT*4)           // 76288 B

__device__ float g_stack[(size_t)Nn * Cc * Hh * Ww];

extern __shared__ float sm[];

__device__ __forceinline__ void csync() {
    asm volatile("barrier.cluster.arrive.aligned;" ::: "memory");
    asm volatile("barrier.cluster.wait.aligned;" ::: "memory");
}
__device__ __forceinline__ unsigned mapa_rank(unsigned laddr, unsigned rank) {
    unsigned ra;
    asm("mapa.shared::cluster.u32 %0, %1, %2;" : "=r"(ra) : "r"(laddr), "r"(rank));
    return ra;
}
__device__ __forceinline__ void st_cl_f32(unsigned a, float v) {
    asm volatile("st.shared::cluster.f32 [%0], %1;" :: "r"(a), "f"(v) : "memory");
}
__device__ __forceinline__ void st_cl_b64(unsigned a, unsigned long long v) {
    asm volatile("st.shared::cluster.b64 [%0], %1;" :: "r"(a), "l"(v) : "memory");
}

// ---- packed f32x2 helpers ----
__device__ __forceinline__ unsigned long long splat2(float a) {
    unsigned long long r; unsigned u = __float_as_uint(a);
    asm("mov.b64 %0, {%1, %1};" : "=l"(r) : "r"(u));
    return r;
}
__device__ __forceinline__ void fma2(unsigned long long& d, unsigned long long a, unsigned long long b) {
    asm("fma.rn.f32x2 %0, %1, %2, %0;" : "+l"(d) : "l"(a), "l"(b));
}
__device__ __forceinline__ unsigned long long add2(unsigned long long a, unsigned long long b) {
    unsigned long long d;
    asm("add.rn.f32x2 %0, %1, %2;" : "=l"(d) : "l"(a), "l"(b));
    return d;
}
__device__ __forceinline__ unsigned long long mul2(unsigned long long a, unsigned long long b) {
    unsigned long long d;
    asm("mul.rn.f32x2 %0, %1, %2;" : "=l"(d) : "l"(a), "l"(b));
    return d;
}
__device__ __forceinline__ void unpack2(unsigned long long v, float& lo, float& hi) {
    unsigned ul, uh;
    asm("mov.b64 {%0, %1}, %2;" : "=r"(ul), "=r"(uh) : "l"(v));
    lo = __uint_as_float(ul); hi = __uint_as_float(uh);
}
__device__ __forceinline__ float elu1(float v) {
    return v > 0.f ? v : (__expf(v) - 1.f);
}

__global__ void __launch_bounds__(NT, 1) __cluster_dims__(Pp, 1, 1)
dirconv_kernel(const float* __restrict__ x, const float* __restrict__ Wg,
               float* __restrict__ out)
{
    float* Ws = sm;
    const unsigned smu = (unsigned)__cvta_generic_to_shared(sm);

    const int tid  = threadIdx.x;
    const int lane = tid & 31;
    const int warp = tid >> 5;
    const int ob   = warp * 8;            // warp's out-channel base
    unsigned rank;
    asm("mov.u32 %0, %%cluster_ctarank;" : "=r"(rank));
    const int g    = (int)rank;           // column group 0..7
    const int w0   = g * 32;
    const int b    = blockIdx.x / Pp;
    const int hasL = (g > 0), hasR = (g < 7);

    const float* xb = x + (size_t)b * Cc * HW;
    float* stk      = g_stack + (size_t)b * Cc * HW;
    float* outb     = out + (size_t)b * Cc * HW;

    const unsigned pbL = mapa_rank(smu, hasL ? rank - 1u : 0u);
    const unsigned pbR = mapa_rank(smu, hasR ? rank + 1u : 0u);
    unsigned pbAll[8];
#pragma unroll
    for (int p2 = 0; p2 < 8; p2++) pbAll[p2] = mapa_rank(smu, (unsigned)p2);

    // stage weights: Ws[i*192 + tap*64 + o] = W[o][i][1][tap] (bias cancels in IN)
    for (int idx = tid; idx < 12288; idx += NT) {
        int i   = idx / 192;
        int rem = idx - i * 192;
        int tap = rem >> 6;
        int o   = rem & 63;
        Ws[idx] = Wg[(size_t)o * 576 + i * 9 + 3 + tap];
    }

    // f[0] = x[0]: full local window [64 ch][34] (edge-masked); own block -> stack row 0
    for (int idx = tid; idx < 2176; idx += NT) {
        int ch = idx / 34;
        int c  = idx - ch * 34;
        int gcol = w0 - 1 + c;
        sm[FB_F(0) + idx] =
            (gcol >= 0 && gcol < Ww) ? xb[(size_t)ch * HW + gcol] : 0.f;
    }
    for (int idx = tid; idx < 2048; idx += NT) {
        int ch = idx >> 5, c = idx & 31;
        stk[(size_t)ch * HW + w0 + c] = xb[(size_t)ch * HW + w0 + c];
    }
    __syncthreads();
    csync();   // all CTAs staged

    float fn[8];   // this thread's fn(t) for (ch = ob+k, col = w0+lane)

    for (int t = 1; t <= 510; ++t) {
        const int p   = t & 1;
        const int fwd = (t <= 255);
        const int row = fwd ? t : 510 - t;
        const float* __restrict__ src = fwd ? xb : stk;
        const float* fbR = sm + FB_F(p ^ 1);
        float* fbW       = sm + FB_F(p);

        // ===== conv: lane = col, warp owns 8 out-ch as 4 f32x2 pairs
        unsigned long long acc0 = 0ull, acc1 = 0ull, acc2 = 0ull, acc3 = 0ull;
#pragma unroll 4
        for (int i = 0; i < Cc; i++) {
            float a0 = fbR[i * FSTR + lane];
            float a1 = fbR[i * FSTR + lane + 1];
            float a2 = fbR[i * FSTR + lane + 2];
            unsigned long long s0 = splat2(a0), s1 = splat2(a1), s2 = splat2(a2);
            const ulonglong2* wp = (const ulonglong2*)(Ws + i * 192 + ob);
            ulonglong2 t0a = wp[0],  t0b = wp[1];    // tap0: ch pairs
            ulonglong2 t1a = wp[16], t1b = wp[17];   // tap1 (+64 floats)
            ulonglong2 t2a = wp[32], t2b = wp[33];   // tap2 (+128 floats)
            fma2(acc0, s0, t0a.x); fma2(acc1, s0, t0a.y);
            fma2(acc2, s0, t0b.x); fma2(acc3, s0, t0b.y);
            fma2(acc0, s1, t1a.x); fma2(acc1, s1, t1a.y);
            fma2(acc2, s1, t1b.x); fma2(acc3, s1, t1b.y);
            fma2(acc0, s2, t2a.x); fma2(acc1, s2, t2a.y);
            fma2(acc2, s2, t2b.x); fma2(acc3, s2, t2b.y);
        }
        float av[8];
        unpack2(acc0, av[0], av[1]);
        unpack2(acc1, av[2], av[3]);
        unpack2(acc2, av[4], av[5]);
        unpack2(acc3, av[6], av[7]);

        // ===== y-halo push: my col31 -> right's left slot, col0 -> left's right slot
        {
            const unsigned yhB = (unsigned)(YH_F(p) * 4);
            if (lane == 31 && hasR) {
#pragma unroll
                for (int k = 0; k < 8; k++)
                    st_cl_f32(pbR + yhB + (unsigned)((ob + k) * 2 + 0) * 4u, av[k]);
            }
            if (lane == 0 && hasL) {
#pragma unroll
                for (int k = 0; k < 8; k++)
                    st_cl_f32(pbL + yhB + (unsigned)((ob + k) * 2 + 1) * 4u, av[k]);
            }
        }

        // ===== butterfly reduce over 32 cols (packed sum / sumsq) + mail push
        {
            unsigned long long s0r = acc0, s1r = acc1, s2r = acc2, s3r = acc3;
            unsigned long long q0r = mul2(acc0, acc0), q1r = mul2(acc1, acc1);
            unsigned long long q2r = mul2(acc2, acc2), q3r = mul2(acc3, acc3);
#pragma unroll
            for (int off = 16; off >= 1; off >>= 1) {
                s0r = add2(s0r, __shfl_xor_sync(0xffffffffu, s0r, off));
                s1r = add2(s1r, __shfl_xor_sync(0xffffffffu, s1r, off));
                s2r = add2(s2r, __shfl_xor_sync(0xffffffffu, s2r, off));
                s3r = add2(s3r, __shfl_xor_sync(0xffffffffu, s3r, off));
                q0r = add2(q0r, __shfl_xor_sync(0xffffffffu, q0r, off));
                q1r = add2(q1r, __shfl_xor_sync(0xffffffffu, q1r, off));
                q2r = add2(q2r, __shfl_xor_sync(0xffffffffu, q2r, off));
                q3r = add2(q3r, __shfl_xor_sync(0xffffffffu, q3r, off));
            }
            if (lane < 8) {
                int j   = lane & 3;
                int isq = lane >> 2;
                unsigned long long val;
                if (isq) val = (j == 0) ? q0r : (j == 1) ? q1r : (j == 2) ? q2r : q3r;
                else     val = (j == 0) ? s0r : (j == 1) ? s1r : (j == 2) ? s2r : s3r;
                unsigned moff = (unsigned)(ML_F(p) * 4) +
                    (unsigned)((int)rank * 128 + isq * 64 + ob + 2 * j) * 4u;
                *(unsigned long long*)((char*)sm + moff) = val;   // local slot
#pragma unroll
                for (int p2 = 0; p2 < 8; p2++)
                    if (p2 != (int)rank) st_cl_b64(pbAll[p2] + moff, val);
            }
        }

        // ===== main residual prefetch (own block; self-written stk rows -> safe here)
        float xr[8];
#pragma unroll
        for (int k = 0; k < 8; k++)
            xr[k] = src[(size_t)(ob + k) * HW + (size_t)row * Ww + w0 + lane];

        // ===== the ONE cluster rendezvous per step
        csync();

        // deferred GMEM writeback of row t-1 (from registers; off the fence path)
        if (t >= 2) {
            const int pfwd = (t - 1) <= 255;
            const int prow = pfwd ? (t - 1) : (511 - t);
            float* __restrict__ pdst = pfwd ? stk : outb;
#pragma unroll
            for (int k = 0; k < 8; k++)
                pdst[(size_t)(ob + k) * HW + (size_t)prow * Ww + w0 + lane] = fn[k];
            if (t == 256) {   // backward init: out[255] = f[255]
#pragma unroll
                for (int k = 0; k < 8; k++)
                    outb[(size_t)(ob + k) * HW + (size_t)255 * Ww + w0 + lane] = fn[k];
            }
        }

        // halo residuals (cross-CTA stk rows -> must come AFTER the csync)
        float xh0 = 0.f, xh1 = 0.f;
        if (tid < 64) {
            if (hasL) xh0 = src[(size_t)tid * HW + (size_t)row * Ww + (w0 - 1)];
            if (hasR) xh1 = src[(size_t)tid * HW + (size_t)row * Ww + (w0 + 32)];
        }

        // ===== stats for all 64 channels (local mail)
        if (tid < 64) {
            const float* ml = sm + ML_F(p);
            float sv = 0.f, qv = 0.f;
#pragma unroll
            for (int r2 = 0; r2 < 8; r2++) {
                sv += ml[r2 * 128 + tid];
                qv += ml[r2 * 128 + 64 + tid];
            }
            float mean = sv * (1.f / 256.f);
            float var  = qv * (1.f / 256.f) - mean * mean;
            sm[MR_F + tid]      = mean;
            sm[MR_F + 64 + tid] = rsqrtf(var + 1e-5f);
        }
        __syncthreads();

        // ===== epilogue: own 32 cols (all warps) + 2 replicated halo cols (tid<64)
#pragma unroll
        for (int k = 0; k < 8; k++) {
            int ch = ob + k;
            float m  = sm[MR_F + ch];
            float rs = sm[MR_F + 64 + ch];
            float f = elu1((av[k] - m) * rs) + xr[k];
            fn[k] = f;
            fbW[ch * FSTR + 1 + lane] = f;
        }
        if (tid < 64) {
            float m  = sm[MR_F + tid];
            float rs = sm[MR_F + 64 + tid];
            const float* yh = sm + YH_F(p);
            fbW[tid * FSTR + 0]  = hasL ? (elu1((yh[tid * 2 + 0] - m) * rs) + xh0) : 0.f;
            fbW[tid * FSTR + 33] = hasR ? (elu1((yh[tid * 2 + 1] - m) * rs) + xh1) : 0.f;
        }
        __syncthreads();   // fbW complete before next conv
    }

    // final writeback: fn holds row 0 (t=510 epilogue output)
#pragma unroll
    for (int k = 0; k < 8; k++)
        outb[(size_t)(ob + k) * HW + w0 + lane] = fn[k];

    // no CTA exits while peers may still push into its smem
    csync();
}

extern "C" void kernel_launch(void* const* d_in, const int* in_sizes, int n_in,
                              void* d_out, int out_size)
{
    (void)in_sizes; (void)n_in; (void)out_size;
    const float* x  = (const float*)d_in[0];
    const float* Wg = (const float*)d_in[1];
    // d_in[2] (bias) cancels through InstanceNorm — skipped.
    float* out = (float*)d_out;

    cudaStreamCaptureStatus cs = cudaStreamCaptureStatusNone;
    cudaStreamIsCapturing(0, &cs);
    if (cs == cudaStreamCaptureStatusNone)
        cudaFuncSetAttribute(dirconv_kernel,
                             cudaFuncAttributeMaxDynamicSharedMemorySize, SMEM_BYTES);

    dirconv_kernel<<<Nn * Pp, NT, SMEM_BYTES>>>(x, Wg, out);
}